// round 17
// baseline (speedup 1.0000x reference)
#include <cuda_runtime.h>
#include <cuda_bf16.h>
#include <cstdint>

#define BATCH 16
#define CIN1  80
#define CMID  256
#define TLEN  4096
#define EMB   128
#define DSTR  12
#define TP    341
#define VQD   16
#define NQ    8
#define NCODE 256

#define EA_SIZE (BATCH*EMB*TP)     // 698368
#define POSN    (BATCH*TP)         // 5456

typedef unsigned long long u64;
typedef __nv_bfloat162 bf2;

// ---------------- helpers ----------------
__device__ __forceinline__ u64 ffma2(u64 a, u64 b, u64 c) {
    u64 d;
    asm("fma.rn.f32x2 %0, %1, %2, %3;" : "=l"(d) : "l"(a), "l"(b), "l"(c));
    return d;
}
__device__ __forceinline__ float2 u2f2(u64 u) {
    float2 f;
    asm("mov.b64 {%0, %1}, %2;" : "=f"(f.x), "=f"(f.y) : "l"(u));
    return f;
}
__device__ __forceinline__ uint32_t smem_u32(const void* p) {
    uint32_t a;
    asm("{ .reg .u64 t; cvta.to.shared.u64 t, %1; cvt.u32.u64 %0, t; }" : "=r"(a) : "l"(p));
    return a;
}
// 3-way bf16 split: x == h + m + l exactly
__device__ __forceinline__ void split3(float x, __nv_bfloat16& h, __nv_bfloat16& m,
                                       __nv_bfloat16& l) {
    h = __float2bfloat16_rn(x);
    float r1 = x - __bfloat162float(h);
    m = __float2bfloat16_rn(r1);
    float r2 = r1 - __bfloat162float(m);
    l = __float2bfloat16_rn(r2);
}
__device__ __forceinline__ unsigned bf2bits(__nv_bfloat16 a, __nv_bfloat16 b) {
    bf2 v = __halves2bfloat162(a, b);
    return *reinterpret_cast<unsigned*>(&v);
}
__device__ __forceinline__ void mma_bf16(float* c, unsigned a0, unsigned a1,
                                         unsigned a2, unsigned a3,
                                         unsigned b0, unsigned b1) {
    asm("mma.sync.aligned.m16n8k16.row.col.f32.bf16.bf16.f32 "
        "{%0,%1,%2,%3}, {%4,%5,%6,%7}, {%8,%9}, {%0,%1,%2,%3};"
        : "+f"(c[0]), "+f"(c[1]), "+f"(c[2]), "+f"(c[3])
        : "r"(a0), "r"(a1), "r"(a2), "r"(a3), "r"(b0), "r"(b1));
}

// -------- scratch --------
__device__ float g_x1[(size_t)BATCH*CMID*TLEN];
__device__ float g_x2[(size_t)BATCH*CMID*TLEN];
__device__ float g_z [(size_t)POSN*VQD];
// quad-packed weights: [chunk][r = kw*8+ci2][co], uint4 = {h_pair, m_pair, l_pair, 0}
#define WQ2_QUADS ((size_t)(CMID/16)*40*CMID)
#define WQ1_QUADS ((size_t)(CIN1/16)*40*CMID)
__device__ uint4 g_wq2[WQ2_QUADS];
__device__ uint4 g_wq1[WQ1_QUADS];

// ============================================================================
// Weight transform: w (256, Cin, 5) -> quad layout
// ============================================================================
__global__ void wtrans_kernel(const float* __restrict__ w,
                              uint4* __restrict__ wq, int Cin)
{
    int idx = blockIdx.x * 256 + threadIdx.x;
    int total = (Cin/16) * 40 * 256;
    if (idx >= total) return;
    int co   = idx & 255;
    int rest = idx >> 8;           // chunk*40 + kw*8 + ci2
    int ci2  = rest & 7;
    int kw   = (rest >> 3) % 5;
    int chunk = rest / 40;
    int ci0 = chunk*16 + 2*ci2;
    float w0 = w[(size_t)co*Cin*5 + (size_t)ci0*5 + kw];
    float w1 = w[(size_t)co*Cin*5 + (size_t)(ci0+1)*5 + kw];
    __nv_bfloat16 h0,m0,l0,h1,m1,l1;
    split3(w0, h0, m0, l0);
    split3(w1, h1, m1, l1);
    uint4 q;
    q.x = bf2bits(h0, h1);
    q.y = bf2bits(m0, m1);
    q.z = bf2bits(l0, l1);
    q.w = 0;
    wq[idx] = q;
}

// ============================================================================
// Implicit-GEMM conv + BN + ReLU, bf16x6 (arithmetic DAG identical to R16).
// Quad-packed smem: one LDS.128 fetches {h,m,l} per fragment position.
// Double-buffered cp.async w + register-staged x overlap mma.
// ============================================================================
#define XSQ 68                 // x quad row stride (8 rows)
#define WSQ 68                 // w quad row stride (40 rows)
#define XQ  (8*XSQ)            // 544 quads
#define WQn (40*WSQ)           // 2720 quads
#define BUFQ (XQ + WQn)        // 3264 quads
#define CONV_SMEM (2*BUFQ*16)  // 104448 B

__global__ __launch_bounds__(256, 2)
void convmma_kernel(const float* __restrict__ X,
                    const uint4* __restrict__ wqg,
                    float* __restrict__ Y, int Cin,
                    const float* __restrict__ cb_, const float* __restrict__ g_,
                    const float* __restrict__ be_, const float* __restrict__ m_,
                    const float* __restrict__ v_)
{
    extern __shared__ uint4 smq[];

    const int t0   = blockIdx.x * 64;
    const int co0  = blockIdx.y * 64;
    const int b    = blockIdx.z;
    const int tid  = threadIdx.x;
    const int lane = tid & 31;
    const int wid  = tid >> 5;
    const int wm   = wid & 3;
    const int wn   = wid >> 2;
    const int qr   = lane >> 2;
    const int qc   = lane & 3;

    const float* Xb = X + (size_t)b * Cin * TLEN;
    const int nchunk = Cin >> 4;

    float cm[4][4];
#pragma unroll
    for (int j = 0; j < 4; j++)
#pragma unroll
        for (int i = 0; i < 4; i++) cm[j][i] = 0.f;

    float xa[3], xb_[3];

#define LDG_X(chunk_)                                                        \
    _Pragma("unroll")                                                        \
    for (int it = 0; it < 3; it++) {                                         \
        int i = tid + it*256;                                                \
        float x0 = 0.f, x1 = 0.f;                                            \
        if (i < 544) {                                                       \
            int ci2 = i / 68, j = i - ci2*68;                                \
            int t = t0 - 2 + j;                                              \
            if (t >= 0 && t < TLEN) {                                        \
                const float* xp = Xb + (size_t)((chunk_)*16 + 2*ci2)*TLEN + t;\
                x0 = xp[0]; x1 = xp[TLEN];                                   \
            }                                                                \
        }                                                                    \
        xa[it] = x0; xb_[it] = x1;                                           \
    }

#define STS_X(dstq)                                                          \
    _Pragma("unroll")                                                        \
    for (int it = 0; it < 3; it++) {                                         \
        int i = tid + it*256;                                                \
        if (i < 544) {                                                       \
            __nv_bfloat16 h0,m0,l0,h1,m1,l1;                                 \
            split3(xa[it], h0, m0, l0);                                      \
            split3(xb_[it], h1, m1, l1);                                     \
            uint4 q;                                                         \
            q.x = bf2bits(h0, h1);                                           \
            q.y = bf2bits(m0, m1);                                           \
            q.z = bf2bits(l0, l1);                                           \
            q.w = 0;                                                         \
            (dstq)[i] = q;                                                   \
        }                                                                    \
    }

#define CPA_W(dstq, chunk_)                                                  \
    {                                                                        \
        const uint4* wsrc = wqg + (size_t)(chunk_) * 40 * 256 + co0;         \
        _Pragma("unroll")                                                    \
        for (int it = 0; it < 10; it++) {                                    \
            int i = tid + it*256;                                            \
            int r = i >> 6, col = i & 63;                                    \
            uint32_t da = smem_u32((dstq) + XQ + r*WSQ + col);               \
            asm volatile("cp.async.cg.shared.global [%0], [%1], 16;"         \
                         :: "r"(da), "l"(wsrc + (size_t)r*256 + col));       \
        }                                                                    \
        asm volatile("cp.async.commit_group;");                              \
    }

    // prologue
    LDG_X(0);
    STS_X(smq);
    CPA_W(smq, 0);

    for (int chunk = 0; chunk < nchunk; chunk++) {
        uint4* buf  = smq + (chunk & 1) * BUFQ;
        uint4* nbuf = smq + ((chunk & 1) ^ 1) * BUFQ;

        asm volatile("cp.async.wait_group 0;" ::: "memory");
        __syncthreads();

        const bool has = (chunk + 1) < nchunk;
        if (has) {
            LDG_X(chunk + 1);
            CPA_W(nbuf, chunk + 1);
        }

        const uint4* xq = buf;
        const uint4* wq = buf + XQ;

#pragma unroll
        for (int kw = 0; kw < 5; kw++) {
            const int ra = (kw*8 + qc)*WSQ + wm*16 + qr;
            const int rb = (kw*8 + qc + 4)*WSQ + wm*16 + qr;
            uint4 A0 = wq[ra], A1 = wq[ra+8], A2 = wq[rb], A3 = wq[rb+8];
#pragma unroll
            for (int j = 0; j < 4; j++) {
                const int toff = wn*32 + j*8 + qr + kw;
                uint4 B0 = xq[qc*XSQ + toff];
                uint4 B1 = xq[(qc+4)*XSQ + toff];
                // identical order to R16: mm, hl, lh, mh, hm, hh
                float ct[4] = {0.f, 0.f, 0.f, 0.f};
                mma_bf16(ct, A0.y,A1.y,A2.y,A3.y, B0.y,B1.y);   // m*m
                mma_bf16(ct, A0.x,A1.x,A2.x,A3.x, B0.z,B1.z);   // h*l
                mma_bf16(ct, A0.z,A1.z,A2.z,A3.z, B0.x,B1.x);   // l*h
                mma_bf16(ct, A0.y,A1.y,A2.y,A3.y, B0.x,B1.x);   // m*h
                mma_bf16(ct, A0.x,A1.x,A2.x,A3.x, B0.y,B1.y);   // h*m
                mma_bf16(ct, A0.x,A1.x,A2.x,A3.x, B0.x,B1.x);   // h*h
#pragma unroll
                for (int i = 0; i < 4; i++) cm[j][i] += ct[i];
            }
        }

        if (has) { STS_X(nbuf); }
    }

    const int r0 = co0 + wm*16 + qr;
    const int r1 = r0 + 8;
    float s0 = g_[r0] * rsqrtf(v_[r0] + 1e-5f);
    float s1 = g_[r1] * rsqrtf(v_[r1] + 1e-5f);
    float bb0 = (cb_[r0] - m_[r0]) * s0 + be_[r0];
    float bb1 = (cb_[r1] - m_[r1]) * s1 + be_[r1];
    float* Y0 = Y + (size_t)b*CMID*TLEN + (size_t)r0*TLEN;
    float* Y1 = Y + (size_t)b*CMID*TLEN + (size_t)r1*TLEN;
#pragma unroll
    for (int j = 0; j < 4; j++) {
        int cn = t0 + wn*32 + j*8 + 2*qc;
        float y00 = fmaf(cm[j][0], s0, bb0); y00 = y00 > 0.f ? y00 : 0.f;
        float y01 = fmaf(cm[j][1], s0, bb0); y01 = y01 > 0.f ? y01 : 0.f;
        float y10 = fmaf(cm[j][2], s1, bb1); y10 = y10 > 0.f ? y10 : 0.f;
        float y11 = fmaf(cm[j][3], s1, bb1); y11 = y11 > 0.f ? y11 : 0.f;
        *(float2*)(Y0 + cn) = make_float2(y00, y01);
        *(float2*)(Y1 + cn) = make_float2(y10, y11);
    }
#undef LDG_X
#undef STS_X
#undef CPA_W
}

// ============================================================================
// Kernel 3: downsample conv — unchanged (exact fp32, LDS.128-paired).
// ============================================================================
#define DC 8
#define D_SMEM (DC*300*8 + DC*24*64*4)

__global__ __launch_bounds__(256, 3)
void down_kernel(const float* __restrict__ wd, const float* __restrict__ bd,
                 float* __restrict__ out)
{
    extern __shared__ float smd[];
    float2* xsd = (float2*)smd;
    float*  ws  = smd + DC*300*2;

    const int tp0 = blockIdx.x * 24;
    const int co0 = blockIdx.y * 64;
    const int b   = blockIdx.z;
    const int tid = threadIdx.x;
    const int cp  = tid & 31;
    const int tg  = tid >> 5;

    const float* xb = g_x2 + (size_t)b*CMID*TLEN;
    const int base = tp0*DSTR - 6;

    u64 acc[3] = {0ull, 0ull, 0ull};

    for (int c0 = 0; c0 < CMID; c0 += DC) {
        __syncthreads();
        for (int i = tid; i < DC*300; i += 256) {
            int ci = i / 300, j = i % 300;
            int t = base + j;
            float v = (t >= 0 && t < TLEN) ? xb[(size_t)(c0+ci)*TLEN + t] : 0.f;
            xsd[i] = make_float2(v, v);
        }
        for (int i = tid; i < DC*24*64; i += 256) {
            int co = i & 63, r = i >> 6;
            ws[i] = wd[(size_t)(co0+co)*(CMID*24) + c0*24 + r];
        }
        __syncthreads();

#pragma unroll 1
        for (int ci = 0; ci < DC; ci++) {
            const u64* xrow = (const u64*)(xsd + ci*300 + tg*36);
            const float* wrow = ws + ci*24*64 + 2*cp;
#pragma unroll 4
            for (int kk = 0; kk < 12; kk++) {
                const int k = 2*kk;
                u64 w0 = *(const u64*)(wrow + k*64);
                u64 w1 = *(const u64*)(wrow + (k+1)*64);
#pragma unroll
                for (int tt = 0; tt < 3; tt++) {
                    ulonglong2 xp = *(const ulonglong2*)(xrow + tt*12 + k);
                    acc[tt] = ffma2(w0, xp.x, acc[tt]);
                    acc[tt] = ffma2(w1, xp.y, acc[tt]);
                }
            }
        }
    }

    const int co = co0 + 2*cp;
    const float b0 = bd[co], b1v = bd[co+1];
#pragma unroll
    for (int tt = 0; tt < 3; tt++) {
        int tp = tp0 + tg*3 + tt;
        if (tp < TP) {
            float2 v = u2f2(acc[tt]);
            out[(size_t)b*EMB*TP + (size_t)co*TP + tp]     = v.x + b0;
            out[(size_t)b*EMB*TP + (size_t)(co+1)*TP + tp] = v.y + b1v;
        }
    }
}

// ============================================================================
// Kernel 4: 1x1 projection (unchanged).
// ============================================================================
__global__ __launch_bounds__(256)
void proj_kernel(const float* __restrict__ out,
                 const float* __restrict__ wp, const float* __restrict__ bp)
{
    __shared__ float xs[EMB*64];
    __shared__ float wps[VQD*EMB];

    const int tp0 = blockIdx.x * 64;
    const int b   = blockIdx.y;
    const int tid = threadIdx.x;
    const int tp_l = tid & 63;
    const int dbase = tid >> 6;

    for (int i = tid; i < EMB*64; i += 256) {
        int e = i >> 6, tl = i & 63;
        int tp = tp0 + tl;
        xs[i] = (tp < TP) ? out[(size_t)b*EMB*TP + (size_t)e*TP + tp] : 0.f;
    }
    for (int i = tid; i < VQD*EMB; i += 256) wps[i] = wp[i];
    __syncthreads();

    float acc[4] = {0.f, 0.f, 0.f, 0.f};
    for (int e = 0; e < EMB; e++) {
        float xv = xs[e*64 + tp_l];
#pragma unroll
        for (int dd = 0; dd < 4; dd++)
            acc[dd] = fmaf(wps[(dd*4 + dbase)*EMB + e], xv, acc[dd]);
    }

    int tp = tp0 + tp_l;
    if (tp < TP) {
#pragma unroll
        for (int dd = 0; dd < 4; dd++) {
            int d = dd*4 + dbase;
            g_z[((size_t)b*TP + tp)*VQD + d] = acc[dd] + bp[d];
        }
    }
}

// ============================================================================
// Kernel 5: residual VQ (unchanged).
// ============================================================================
__global__ __launch_bounds__(256)
void rvq_kernel(const float* __restrict__ codebooks, float* __restrict__ out)
{
    __shared__ float cbs[NCODE * VQD];
    __shared__ float cc[NCODE];

    const int tid = threadIdx.x;
    const int pos = blockIdx.x * 256 + tid;
    const bool valid = pos < POSN;

    float r[VQD];
    if (valid) {
#pragma unroll
        for (int d = 0; d < VQD; d++) r[d] = g_z[(size_t)pos*VQD + d];
    }

    for (int q = 0; q < NQ; q++) {
        __syncthreads();
        for (int i = tid; i < NCODE*VQD; i += 256)
            cbs[i] = codebooks[(size_t)q*NCODE*VQD + i];
        __syncthreads();
        {
            float s = 0.f;
#pragma unroll
            for (int d = 0; d < VQD; d++) {
                float c = cbs[tid*VQD + d];
                s = fmaf(c, c, s);
            }
            cc[tid] = s;
        }
        __syncthreads();

        if (valid) {
            int best = 0;
            float bestd = 3.4e38f;
            for (int code = 0; code < NCODE; code++) {
                float dot = 0.f;
#pragma unroll
                for (int d = 0; d < VQD; d++)
                    dot = fmaf(r[d], cbs[code*VQD + d], dot);
                float sc = cc[code] - 2.f*dot;
                if (sc < bestd) { bestd = sc; best = code; }
            }
            out[EA_SIZE + (size_t)q*POSN + pos] = (float)best;
#pragma unroll
            for (int d = 0; d < VQD; d++) r[d] -= cbs[best*VQD + d];
        }
    }
}

// ============================================================================
extern "C" void kernel_launch(void* const* d_in, const int* in_sizes, int n_in,
                              void* d_out, int out_size)
{
    const float* mel = (const float*)d_in[0];
    const float* w1  = (const float*)d_in[1];
    const float* b1  = (const float*)d_in[2];
    const float* g1  = (const float*)d_in[3];
    const float* be1 = (const float*)d_in[4];
    const float* m1  = (const float*)d_in[5];
    const float* v1  = (const float*)d_in[6];
    const float* w2  = (const float*)d_in[7];
    const float* b2  = (const float*)d_in[8];
    const float* g2  = (const float*)d_in[9];
    const float* be2 = (const float*)d_in[10];
    const float* m2  = (const float*)d_in[11];
    const float* v2  = (const float*)d_in[12];
    const float* wd  = (const float*)d_in[13];
    const float* bd  = (const float*)d_in[14];
    const float* wp  = (const float*)d_in[15];
    const float* bp  = (const float*)d_in[16];
    const float* cb  = (const float*)d_in[17];
    float* out = (float*)d_out;

    uint4 *wq2p, *wq1p;
    cudaGetSymbolAddress((void**)&wq2p, g_wq2);
    cudaGetSymbolAddress((void**)&wq1p, g_wq1);
    float *x1p, *x2p;
    cudaGetSymbolAddress((void**)&x1p, g_x1);
    cudaGetSymbolAddress((void**)&x2p, g_x2);

    cudaFuncSetAttribute(convmma_kernel, cudaFuncAttributeMaxDynamicSharedMemorySize, CONV_SMEM);
    cudaFuncSetAttribute(down_kernel,    cudaFuncAttributeMaxDynamicSharedMemorySize, D_SMEM);

    wtrans_kernel<<<((CMID/16)*40*256 + 255)/256, 256>>>(w2, wq2p, CMID);             // 0
    wtrans_kernel<<<((CIN1/16)*40*256 + 255)/256, 256>>>(w1, wq1p, CIN1);             // 1
    convmma_kernel<<<dim3(TLEN/64, CMID/64, BATCH), 256, CONV_SMEM>>>(                 // 2
        mel, wq1p, x1p, CIN1, b1, g1, be1, m1, v1);
    convmma_kernel<<<dim3(TLEN/64, CMID/64, BATCH), 256, CONV_SMEM>>>(                 // 3
        x1p, wq2p, x2p, CMID, b2, g2, be2, m2, v2);
    down_kernel<<<dim3((TP + 23)/24, EMB/64, BATCH), 256, D_SMEM>>>(wd, bd, out);      // 4
    proj_kernel<<<dim3((TP + 63)/64, BATCH), 256>>>(out, wp, bp);                      // 5
    rvq_kernel<<<(POSN + 255)/256, 256>>>(cb, out);                                    // 6
}